// round 5
// baseline (speedup 1.0000x reference)
#include <cuda_runtime.h>

#define H_IMG 512
#define W_IMG 512
#define NPLANES 96            // 32 * 3
#define TW 32
#define TH 64
#define IW 42                 // TW + 10
#define IH 74                 // TH + 10
#define SS 43                 // staged-input stride in float2 units
#define MS 33                 // intermediate stride in float2 units
#define NT 256
#define NBX 16                // 512/32
#define NBY 8                 // 512/64
#define NBLK (NBX * NBY * NPLANES)   // 12288
#define C1F 6.5025f
#define C2F 58.5225f
#define NPIX 25165824.0       // 32*3*512*512

// dynamic smem (float2 units): staged (g,r) + packed (m1,m2) + packed (ss,gr)
#define SMEM_F2 (IH * SS + 2 * IH * MS)

typedef unsigned long long u64;

__device__ float g_partials[NBLK];
__device__ unsigned int g_count = 0;

#define W11_INIT {0.00102838f, 0.00759871f, 0.03600077f, 0.10936070f, \
                  0.21300560f, 0.26601180f, 0.21300560f, 0.10936070f, \
                  0.03600077f, 0.00759871f, 0.00102838f}

__forceinline__ __device__ u64 ffma2(u64 a, u64 b, u64 c) {
    u64 d;
    asm("fma.rn.f32x2 %0, %1, %2, %3;" : "=l"(d) : "l"(a), "l"(b), "l"(c));
    return d;
}
__forceinline__ __device__ u64 pack2(float lo, float hi) {
    u64 d;
    asm("mov.b64 %0, {%1, %2};" : "=l"(d) : "f"(lo), "f"(hi));
    return d;
}
__forceinline__ __device__ void unpack2(u64 v, float& lo, float& hi) {
    asm("mov.b64 {%0, %1}, %2;" : "=f"(lo), "=f"(hi) : "l"(v));
}

__global__ void __launch_bounds__(NT, 3) ssim_main(const float* __restrict__ gen,
                                                   const float* __restrict__ ref,
                                                   float* __restrict__ out) {
    extern __shared__ u64 smem2[];
    u64* sgr = smem2;                 // IH*SS   packed (g, r)
    u64* pmu = sgr + IH * SS;         // IH*MS   packed (conv_h g, conv_h r)
    u64* psg = pmu + IH * MS;         // IH*MS   packed (conv_h g^2+r^2, conv_h g*r)

    __shared__ u64 ws2[11];           // packed (w, w)
    __shared__ float wsum[8];
    __shared__ double dsum[8];
    __shared__ bool is_last;

    const float W11[11] = W11_INIT;

    const int tid = threadIdx.x;
    const int lane = tid & 31;
    const int wrp = tid >> 5;
    const int x0 = blockIdx.x * TW;
    const int y0 = blockIdx.y * TH;
    const size_t pb = (size_t)blockIdx.z * (size_t)(H_IMG * W_IMG);
    const float* gp = gen + pb;
    const float* rp = ref + pb;

    if (tid < 11) ws2[tid] = pack2(W11[tid], W11[tid]);

    // ---- Stage 0: coalesced load tile+halo, scale, zero-pad, pack (g,r) ----
    for (int i = tid; i < IH * IW; i += NT) {
        int r = i / IW;
        int c = i - r * IW;
        int gy = y0 + r - 5;
        int gx = x0 + c - 5;
        float gv = 0.f, rv = 0.f;
        if ((unsigned)gy < (unsigned)H_IMG && (unsigned)gx < (unsigned)W_IMG) {
            int idx = gy * W_IMG + gx;
            gv = fmaf(gp[idx], 0.5f, 0.5f);
            rv = fmaf(rp[idx], 0.5f, 0.5f);
        }
        sgr[r * SS + c] = pack2(gv, rv);
    }
    __syncthreads();

    // ---- Stage 1: packed horizontal conv, 4 cols per lane-item ----
    // groups of 4 rows x 8 chunks; lane -> (chunk = lane>>2, rowoff = lane&3)
    // (this mapping is conflict-free for 64-bit LDS phases)
    for (int g = wrp; g < 19; g += 8) {
        int r = (g << 2) + (lane & 3);
        if (r >= IH) continue;
        int c0 = (lane >> 2) << 2;
        const u64* srow = sgr + r * SS + c0;
        const int o = r * MS + c0;

        u64 a2[14];
#pragma unroll
        for (int t = 0; t < 14; t++) a2[t] = srow[t];

        // first moments: packed (m1, m2)
        {
            u64 s[4] = {0ull, 0ull, 0ull, 0ull};
#pragma unroll
            for (int k = 0; k < 11; k++) {
                u64 w2 = ws2[k];
#pragma unroll
                for (int j = 0; j < 4; j++) s[j] = ffma2(w2, a2[k + j], s[j]);
            }
#pragma unroll
            for (int j = 0; j < 4; j++) pmu[o + j] = s[j];
        }

        // in-place transform: a2 <- (g^2 + r^2, g*r)
#pragma unroll
        for (int t = 0; t < 14; t++) {
            float gv, rv;
            unpack2(a2[t], gv, rv);
            a2[t] = pack2(fmaf(gv, gv, rv * rv), gv * rv);
        }

        // second moments: packed (ss, gr)
        {
            u64 s[4] = {0ull, 0ull, 0ull, 0ull};
#pragma unroll
            for (int k = 0; k < 11; k++) {
                u64 w2 = ws2[k];
#pragma unroll
                for (int j = 0; j < 4; j++) s[j] = ffma2(w2, a2[k + j], s[j]);
            }
#pragma unroll
            for (int j = 0; j < 4; j++) psg[o + j] = s[j];
        }
    }
    __syncthreads();

    // ---- Stage 2: packed vertical conv (4-row strips x 2) + SSIM ----
    float lsum = 0.f;
#pragma unroll
    for (int it = 0; it < 2; it++) {
        const int r0 = ((wrp + (it << 3)) << 2);   // 0..60
        const int c = lane;

        float q[4], p[4];
        {
            u64 v[14];
#pragma unroll
            for (int t = 0; t < 14; t++) v[t] = pmu[(r0 + t) * MS + c];
#pragma unroll
            for (int j = 0; j < 4; j++) {
                u64 acc = 0ull;
#pragma unroll
                for (int k = 0; k < 11; k++) acc = ffma2(ws2[k], v[j + k], acc);
                float mu1, mu2;
                unpack2(acc, mu1, mu2);
                q[j] = fmaf(mu1, mu1, mu2 * mu2);
                p[j] = mu1 * mu2;
            }
        }
        {
            u64 v[14];
#pragma unroll
            for (int t = 0; t < 14; t++) v[t] = psg[(r0 + t) * MS + c];
#pragma unroll
            for (int j = 0; j < 4; j++) {
                u64 acc = 0ull;
#pragma unroll
                for (int k = 0; k < 11; k++) acc = ffma2(ws2[k], v[j + k], acc);
                float oss, ogr;
                unpack2(acc, oss, ogr);
                float num = fmaf(2.f, p[j], C1F) * fmaf(2.f, ogr - p[j], C2F);
                float den = (q[j] + C1F) * (oss - q[j] + C2F);
                lsum += __fdividef(num, den);
            }
        }
    }

    // ---- Block reduction (fp32) ----
#pragma unroll
    for (int off = 16; off > 0; off >>= 1)
        lsum += __shfl_xor_sync(0xffffffffu, lsum, off);
    if (lane == 0) wsum[wrp] = lsum;
    __syncthreads();

    if (tid == 0) {
        float s = 0.f;
#pragma unroll
        for (int i = 0; i < 8; i++) s += wsum[i];
        int bid = blockIdx.x + NBX * (blockIdx.y + NBY * blockIdx.z);
        g_partials[bid] = s;
        __threadfence();
        unsigned int t = atomicAdd(&g_count, 1u);
        is_last = (t == (unsigned)(NBLK - 1));
    }
    __syncthreads();

    // ---- Last block: deterministic final reduction ----
    if (is_last) {
        __threadfence();
        double acc = 0.0;
        for (int i = tid; i < NBLK; i += NT)
            acc += (double)g_partials[i];
#pragma unroll
        for (int off = 16; off > 0; off >>= 1)
            acc += __shfl_xor_sync(0xffffffffu, acc, off);
        if (lane == 0) dsum[wrp] = acc;
        __syncthreads();
        if (tid == 0) {
            double s = 0.0;
#pragma unroll
            for (int i = 0; i < 8; i++) s += dsum[i];
            out[0] = (float)(1.0 - s / NPIX);
            g_count = 0;   // self-reset -> graph-replay deterministic
        }
    }
}

extern "C" void kernel_launch(void* const* d_in, const int* in_sizes, int n_in,
                              void* d_out, int out_size) {
    const float* gen = (const float*)d_in[0];
    const float* ref = (const float*)d_in[1];
    float* out = (float*)d_out;

    size_t shmem = (size_t)SMEM_F2 * sizeof(u64);   // ~64.5KB
    cudaFuncSetAttribute(ssim_main, cudaFuncAttributeMaxDynamicSharedMemorySize,
                         (int)shmem);

    dim3 grid(NBX, NBY, NPLANES);
    ssim_main<<<grid, NT, shmem>>>(gen, ref, out);
}

// round 6
// speedup vs baseline: 1.2219x; 1.2219x over previous
#include <cuda_runtime.h>

#define H_IMG 512
#define W_IMG 512
#define NPLANES 96            // 32 * 3
#define TW 32
#define TH 32
#define IW 42                 // TW + 10
#define IH 42                 // TH + 10
#define SS 43                 // staged-input smem row stride (odd -> conflict-free)
#define MS 33                 // intermediate smem row stride (conflict-free)
#define NT 256
#define NBX 16                // 512/32
#define NBY 16                // 512/32
#define NBLK (NBX * NBY * NPLANES)   // 24576
#define C1F 6.5025f
#define C2F 58.5225f
#define NPIX 25165824.0       // 32*3*512*512

__device__ float g_partials[NBLK];
__device__ unsigned int g_count = 0;

#define W11_INIT {0.00102838f, 0.00759871f, 0.03600077f, 0.10936070f, \
                  0.21300560f, 0.26601180f, 0.21300560f, 0.10936070f, \
                  0.03600077f, 0.00759871f, 0.00102838f}

__global__ void __launch_bounds__(NT, 4) ssim_main(const float* __restrict__ gen,
                                                   const float* __restrict__ ref,
                                                   float* __restrict__ out) {
    __shared__ float sg[IH * SS];      // staged gen (scaled)
    __shared__ float sr[IH * SS];      // staged ref (scaled)
    __shared__ float m1[IH * MS];      // conv_h(g)
    __shared__ float m2[IH * MS];      // conv_h(r)
    __shared__ float mss[IH * MS];     // conv_h(g^2 + r^2)
    __shared__ float mgr[IH * MS];     // conv_h(g*r)
    __shared__ float wsum[8];
    __shared__ double dsum[8];
    __shared__ bool is_last;

    const float W11[11] = W11_INIT;    // compile-time consts -> FFMA-imm

    const int tid = threadIdx.x;
    const int lane = tid & 31;
    const int wrp = tid >> 5;
    const int x0 = blockIdx.x * TW;
    const int y0 = blockIdx.y * TH;
    const size_t pb = (size_t)blockIdx.z * (size_t)(H_IMG * W_IMG);
    const float* gp = gen + pb;
    const float* rp = ref + pb;

    // ---- Stage 0: coalesced load of tile+halo, scale, zero-pad ----
    const bool interior = (x0 >= 5) & (x0 + IW - 5 <= W_IMG) &
                          (y0 >= 5) & (y0 + IH - 5 <= H_IMG);
    if (interior) {
        const float* gb = gp + (long)(y0 - 5) * W_IMG + (x0 - 5);
        const float* rb = rp + (long)(y0 - 5) * W_IMG + (x0 - 5);
#pragma unroll 2
        for (int i = tid; i < IH * IW; i += NT) {
            int r = i / IW;
            int c = i - r * IW;
            int idx = r * W_IMG + c;
            sg[r * SS + c] = fmaf(gb[idx], 0.5f, 0.5f);
            sr[r * SS + c] = fmaf(rb[idx], 0.5f, 0.5f);
        }
    } else {
#pragma unroll 2
        for (int i = tid; i < IH * IW; i += NT) {
            int r = i / IW;
            int c = i - r * IW;
            int gy = y0 + r - 5;
            int gx = x0 + c - 5;
            float gv = 0.f, rv = 0.f;
            if ((unsigned)gy < (unsigned)H_IMG && (unsigned)gx < (unsigned)W_IMG) {
                int idx = gy * W_IMG + gx;
                gv = fmaf(gp[idx], 0.5f, 0.5f);
                rv = fmaf(rp[idx], 0.5f, 0.5f);
            }
            sg[r * SS + c] = gv;
            sr[r * SS + c] = rv;
        }
    }
    __syncthreads();

    // ---- Stage 1: horizontal conv, 4 fields, 4 output cols per item ----
    // items: 42 rows x 8 col-chunks of 4 = 336
    for (int item = tid; item < IH * 8; item += NT) {
        int r = item >> 3;
        int c0 = (item & 7) << 2;
        const float* sgr = sg + r * SS + c0;
        const float* srr = sr + r * SS + c0;
        const int o = r * MS + c0;

        float a[14], b[14];
#pragma unroll
        for (int t = 0; t < 14; t++) { a[t] = sgr[t]; b[t] = srr[t]; }

        // first moments
        {
            float s1[4] = {0.f, 0.f, 0.f, 0.f};
            float s2[4] = {0.f, 0.f, 0.f, 0.f};
#pragma unroll
            for (int k = 0; k < 11; k++) {
#pragma unroll
                for (int j = 0; j < 4; j++) {
                    s1[j] = fmaf(W11[k], a[k + j], s1[j]);
                    s2[j] = fmaf(W11[k], b[k + j], s2[j]);
                }
            }
#pragma unroll
            for (int j = 0; j < 4; j++) { m1[o + j] = s1[j]; m2[o + j] = s2[j]; }
        }

        // in-place transform: a <- g^2 + r^2,  b <- g*r
#pragma unroll
        for (int t = 0; t < 14; t++) {
            float pa = a[t];
            float pbv = b[t];
            a[t] = fmaf(pa, pa, pbv * pbv);
            b[t] = pa * pbv;
        }

        // second moments
        {
            float s3[4] = {0.f, 0.f, 0.f, 0.f};
            float s4[4] = {0.f, 0.f, 0.f, 0.f};
#pragma unroll
            for (int k = 0; k < 11; k++) {
#pragma unroll
                for (int j = 0; j < 4; j++) {
                    s3[j] = fmaf(W11[k], a[k + j], s3[j]);
                    s4[j] = fmaf(W11[k], b[k + j], s4[j]);
                }
            }
#pragma unroll
            for (int j = 0; j < 4; j++) { mss[o + j] = s3[j]; mgr[o + j] = s4[j]; }
        }
    }
    __syncthreads();

    // ---- Stage 2: vertical conv (4 rows/thread), streaming SSIM combine ----
    float lsum = 0.f;
    {
        const int c = lane;
        const int r0 = wrp << 2;       // 8 warps * 4 rows = 32

#define VCONV(MARR, OUT)                                                  \
        {                                                                 \
            float v[14];                                                  \
            _Pragma("unroll")                                             \
            for (int t = 0; t < 14; t++) v[t] = MARR[(r0 + t) * MS + c];  \
            _Pragma("unroll")                                             \
            for (int j = 0; j < 4; j++) {                                 \
                float acc = 0.f;                                          \
                _Pragma("unroll")                                         \
                for (int k = 0; k < 11; k++)                              \
                    acc = fmaf(W11[k], v[j + k], acc);                    \
                OUT[j] = acc;                                             \
            }                                                             \
        }

        float q[4], p[4];              // mu1^2+mu2^2, mu1*mu2
        {
            float o1[4], o2[4];
            VCONV(m1, o1)
            VCONV(m2, o2)
#pragma unroll
            for (int j = 0; j < 4; j++) {
                q[j] = fmaf(o1[j], o1[j], o2[j] * o2[j]);
                p[j] = o1[j] * o2[j];
            }
        }
        float dden[4];
        {
            float oss[4];
            VCONV(mss, oss)
#pragma unroll
            for (int j = 0; j < 4; j++)
                dden[j] = (q[j] + C1F) * (oss[j] - q[j] + C2F);
        }
        {
            float ogr[4];
            VCONV(mgr, ogr)
#pragma unroll
            for (int j = 0; j < 4; j++) {
                float num = fmaf(2.f, p[j], C1F) * fmaf(2.f, ogr[j] - p[j], C2F);
                lsum += __fdividef(num, dden[j]);
            }
        }
#undef VCONV
    }

    // ---- Block reduction (fp32) ----
#pragma unroll
    for (int off = 16; off > 0; off >>= 1)
        lsum += __shfl_xor_sync(0xffffffffu, lsum, off);
    if (lane == 0) wsum[wrp] = lsum;
    __syncthreads();

    if (tid == 0) {
        float s = 0.f;
#pragma unroll
        for (int i = 0; i < 8; i++) s += wsum[i];
        int bid = blockIdx.x + NBX * (blockIdx.y + NBY * blockIdx.z);
        g_partials[bid] = s;
        __threadfence();
        unsigned int t = atomicAdd(&g_count, 1u);
        is_last = (t == (unsigned)(NBLK - 1));
    }
    __syncthreads();

    // ---- Last block: deterministic final reduction ----
    if (is_last) {
        __threadfence();
        double acc = 0.0;
        for (int i = tid; i < NBLK; i += NT)
            acc += (double)g_partials[i];
#pragma unroll
        for (int off = 16; off > 0; off >>= 1)
            acc += __shfl_xor_sync(0xffffffffu, acc, off);
        if (lane == 0) dsum[wrp] = acc;
        __syncthreads();
        if (tid == 0) {
            double s = 0.0;
#pragma unroll
            for (int i = 0; i < 8; i++) s += dsum[i];
            out[0] = (float)(1.0 - s / NPIX);
            g_count = 0;   // self-reset -> graph-replay deterministic
        }
    }
}

extern "C" void kernel_launch(void* const* d_in, const int* in_sizes, int n_in,
                              void* d_out, int out_size) {
    const float* gen = (const float*)d_in[0];
    const float* ref = (const float*)d_in[1];
    float* out = (float*)d_out;

    dim3 grid(NBX, NBY, NPLANES);
    ssim_main<<<grid, NT>>>(gen, ref, out);
}